// round 14
// baseline (speedup 1.0000x reference)
#include <cuda_runtime.h>
#include <cuda_bf16.h>

// out[i,j] = log1p(max(0, Gauss9 ⊛ T)),  T[i,j] = Resize2x(img)[N-1-j, i] + 0.01*noise[i,j]
// Resize2x = jax.image.resize 'linear' (half-pixel centers, 2x => weights {0.25,0.75}, edge clamp)
// Blur: separable 9-tap sigma=1 Gaussian, numpy 'symmetric' padding on T.

#define NN 4096
#define MM 2048
#define TI 64
#define TJ 64
#define HALO 4
#define LI (TI + 2*HALO)   // 72
#define LJ (TJ + 2*HALO)   // 72
#define P1 73              // s1 pitch (odd -> conflict-free column access)
#define P2 76              // s2 pitch (mult of 4 -> aligned float4 loads)

__device__ __forceinline__ int symidx(int p) {
    p = (p < 0) ? (-1 - p) : p;
    return (p >= NN) ? (2 * NN - 1 - p) : p;
}

__global__ __launch_bounds__(256, 5)
void fused_aug_kernel(const float* __restrict__ img,
                      const float* __restrict__ noise,
                      float* __restrict__ out)
{
    __shared__ float s1[LI * P1];                 // T tile + halo (img part for interior)
    __shared__ __align__(16) float s2[TI * P2];   // vertically blurred

    const float KW[9] = {1.3383062e-4f, 4.4318616e-3f, 5.3991124e-2f,
                         2.4197145e-1f, 3.9894347e-1f, 2.4197145e-1f,
                         5.3991124e-2f, 4.4318616e-3f, 1.3383062e-4f};

    const int t  = threadIdx.x;
    const int bx = (int)blockIdx.x;
    const int by = (int)blockIdx.y;
    const int i0 = by * TI - HALO;
    const int j0 = bx * TJ - HALO;
    const bool edge = (bx == 0) | (by == 0) | (bx == 63) | (by == 63);

    if (!edge) {
        // ---- Phase A (interior): rotated 2x-resize, 2x2 outputs/thread ----
        for (int idx = t; idx < 35 * 36; idx += 256) {
            int c  = idx / 36;
            int m  = idx - c * 36;
            int jj = 2 * c + 1;
            int ii = 2 * m;
            int a  = 4095 - (j0 + jj);            // even
            int p  = a >> 1;
            const float* r0 = img + (size_t)(p - 1) * MM;
            const float* r1 = r0 + MM;
            int k = (i0 + ii) >> 1;
            float A0 = __ldg(&r0[k - 1]);
            float A1 = __ldg(&r0[k]);
            float A2 = __ldg(&r0[k + 1]);
            float B0 = __ldg(&r1[k - 1]);
            float B1 = __ldg(&r1[k]);
            float B2 = __ldg(&r1[k + 1]);
            float ea = fmaf(0.25f, A0, 0.75f * A1);
            float oa = fmaf(0.75f, A1, 0.25f * A2);
            float eb = fmaf(0.25f, B0, 0.75f * B1);
            float ob = fmaf(0.75f, B1, 0.25f * B2);
            float* s = s1 + ii * P1 + jj;
            s[0]      = fmaf(0.25f, ea, 0.75f * eb);
            s[1]      = fmaf(0.75f, ea, 0.25f * eb);
            s[P1]     = fmaf(0.25f, oa, 0.75f * ob);
            s[P1 + 1] = fmaf(0.75f, oa, 0.25f * ob);
        }
        // Leftover columns jj = 0 and jj = 71
        if (t < 72) {
            int col = t / 36;
            int m   = t - col * 36;
            int jj  = col ? (LJ - 1) : 0;
            int ii  = 2 * m;
            int a   = 4095 - (j0 + jj);
            int yf  = (a - 1) >> 1;
            float fy = (a & 1) ? 0.25f : 0.75f;
            const float* r0 = img + (size_t)yf * MM;
            const float* r1 = r0 + MM;
            int k = (i0 + ii) >> 1;
            float A0 = __ldg(&r0[k - 1]);
            float A1 = __ldg(&r0[k]);
            float A2 = __ldg(&r0[k + 1]);
            float B0 = __ldg(&r1[k - 1]);
            float B1 = __ldg(&r1[k]);
            float B2 = __ldg(&r1[k + 1]);
            float ea = fmaf(0.25f, A0, 0.75f * A1);
            float oa = fmaf(0.75f, A1, 0.25f * A2);
            float eb = fmaf(0.25f, B0, 0.75f * B1);
            float ob = fmaf(0.75f, B1, 0.25f * B2);
            s1[ii * P1 + jj]       = fmaf(fy, eb - ea, ea);
            s1[(ii + 1) * P1 + jj] = fmaf(fy, ob - oa, oa);
        }
        __syncthreads();

        // ---- Phase C (interior): noise fused into vertical blur, 8-row strips ----
        for (int idx = t; idx < 8 * LJ; idx += 256) {   // 576 tasks
            int g  = idx / LJ;
            int jj = idx - g * LJ;
            int ii = g * 8;
            const float* np = noise + (size_t)(i0 + ii) * NN + (j0 + jj);
            float v[16];
            #pragma unroll
            for (int r = 0; r < 16; r++)
                v[r] = fmaf(0.01f, __ldg(&np[(size_t)r * NN]), s1[(ii + r) * P1 + jj]);
            #pragma unroll
            for (int r = 0; r < 8; r++) {
                float acc = 0.0f;
                #pragma unroll
                for (int d = 0; d < 9; d++) acc = fmaf(KW[d], v[r + d], acc);
                s2[(ii + r) * P2 + jj] = acc;
            }
        }
    } else {
        // ---- Phase A (edge): symidx + clamps ----
        #pragma unroll 3
        for (int idx = t; idx < LI * LJ; idx += 256) {
            int jj = idx / LI;
            int ii = idx - jj * LI;
            int a  = NN - 1 - symidx(j0 + jj);
            int b  = symidx(i0 + ii);
            int yf = (a - 1) >> 1;
            int xf = (b - 1) >> 1;
            int y0 = max(yf, 0), y1 = min(yf + 1, MM - 1);
            int x0 = max(xf, 0), x1 = min(xf + 1, MM - 1);
            float fy = (a & 1) ? 0.25f : 0.75f;
            float fx = (b & 1) ? 0.25f : 0.75f;
            const float* r0 = img + (size_t)y0 * MM;
            const float* r1 = img + (size_t)y1 * MM;
            float v0 = __ldg(&r0[x0]);
            float v1 = __ldg(&r0[x1]);
            float w0 = __ldg(&r1[x0]);
            float w1 = __ldg(&r1[x1]);
            float h0 = fmaf(fx, v1 - v0, v0);
            float h1 = fmaf(fx, w1 - w0, w0);
            s1[ii * P1 + jj] = fmaf(fy, h1 - h0, h0);
        }
        __syncthreads();

        // ---- Phase B (edge): add noise with symidx ----
        #pragma unroll 3
        for (int idx = t; idx < LI * LJ; idx += 256) {
            int ii = idx / LJ;
            int jj = idx - ii * LJ;
            int gi = symidx(i0 + ii);
            int gj = symidx(j0 + jj);
            s1[ii * P1 + jj] += 0.01f * __ldg(&noise[(size_t)gi * NN + gj]);
        }
        __syncthreads();

        // ---- Phase C (edge): vertical blur, 8-row strips ----
        for (int idx = t; idx < 8 * LJ; idx += 256) {
            int g  = idx / LJ;
            int jj = idx - g * LJ;
            int ii = g * 8;
            float v[16];
            #pragma unroll
            for (int r = 0; r < 16; r++) v[r] = s1[(ii + r) * P1 + jj];
            #pragma unroll
            for (int r = 0; r < 8; r++) {
                float acc = 0.0f;
                #pragma unroll
                for (int d = 0; d < 9; d++) acc = fmaf(KW[d], v[r + d], acc);
                s2[(ii + r) * P2 + jj] = acc;
            }
        }
    }
    __syncthreads();

    // ---- Phase D: horizontal blur + clip + fast log1p, 16 outputs/thread ----
    // 256 tasks = exactly one dense round; 24-float window for 16 outputs (1.5x re-read).
    {
        const int oi0 = by * TI;
        const int oj0 = bx * TJ;
        int ii = t >> 2;                // 0..63
        int jj = (t & 3) * 16;          // 0,16,32,48
        const float* row = &s2[ii * P2 + jj];
        float4 c0 = *(const float4*)(row);
        float4 c1 = *(const float4*)(row + 4);
        float4 c2 = *(const float4*)(row + 8);
        float4 c3 = *(const float4*)(row + 12);
        float4 c4 = *(const float4*)(row + 16);
        float4 c5 = *(const float4*)(row + 20);
        float v[24] = {c0.x, c0.y, c0.z, c0.w,  c1.x, c1.y, c1.z, c1.w,
                       c2.x, c2.y, c2.z, c2.w,  c3.x, c3.y, c3.z, c3.w,
                       c4.x, c4.y, c4.z, c4.w,  c5.x, c5.y, c5.z, c5.w};
        float* dst = &out[(size_t)(oi0 + ii) * NN + (oj0 + jj)];
        #pragma unroll
        for (int q = 0; q < 4; q++) {
            float res[4];
            #pragma unroll
            for (int r = 0; r < 4; r++) {
                float acc = 0.0f;
                #pragma unroll
                for (int d = 0; d < 9; d++) acc = fmaf(KW[d], v[q * 4 + r + d], acc);
                res[r] = __logf(1.0f + fmaxf(acc, 0.0f));
            }
            *(float4*)(dst + q * 4) = make_float4(res[0], res[1], res[2], res[3]);
        }
    }
}

extern "C" void kernel_launch(void* const* d_in, const int* in_sizes, int n_in,
                              void* d_out, int out_size) {
    const float* img   = (const float*)d_in[0];   // (1,2048,2048) f32
    const float* noise = (const float*)d_in[1];   // (1,4096,4096) f32
    if (n_in >= 2 && in_sizes[0] > in_sizes[1]) {
        const float* tmp = img; img = noise; noise = tmp;
    }
    dim3 grid(NN / TJ, NN / TI);
    fused_aug_kernel<<<grid, 256>>>(img, noise, (float*)d_out);
}

// round 16
// speedup vs baseline: 1.1300x; 1.1300x over previous
#include <cuda_runtime.h>
#include <cuda_bf16.h>

// out[i,j] = log1p(max(0, Gauss9 ⊛ T)),  T[i,j] = Resize2x(img)[N-1-j, i] + 0.01*noise[i,j]
// Resize2x = jax.image.resize 'linear' (half-pixel centers, 2x => weights {0.25,0.75}, edge clamp)
// Blur: separable 9-tap sigma=1 Gaussian, numpy 'symmetric' padding on T.

#define NN 4096
#define MM 2048
#define TI 64
#define TJ 64
#define HALO 4
#define LI (TI + 2*HALO)   // 72
#define LJ (TJ + 2*HALO)   // 72
#define P1 73              // s1 pitch (odd -> conflict-free strided access)
#define P2 76              // s2 pitch (mult of 4 -> aligned float4 loads)

__device__ __forceinline__ int symidx(int p) {
    p = (p < 0) ? (-1 - p) : p;
    return (p >= NN) ? (2 * NN - 1 - p) : p;
}

__global__ __launch_bounds__(256, 5)
void fused_aug_kernel(const float* __restrict__ img,
                      const float* __restrict__ noise,
                      float* __restrict__ out)
{
    __shared__ float s1[LI * P1];                 // T tile + halo (img part for interior)
    __shared__ __align__(16) float s2[TI * P2];   // vertically blurred

    const float KW[9] = {1.3383062e-4f, 4.4318616e-3f, 5.3991124e-2f,
                         2.4197145e-1f, 3.9894347e-1f, 2.4197145e-1f,
                         5.3991124e-2f, 4.4318616e-3f, 1.3383062e-4f};

    const int t  = threadIdx.x;
    const int bx = (int)blockIdx.x;
    const int by = (int)blockIdx.y;
    const int i0 = by * TI - HALO;
    const int j0 = bx * TJ - HALO;
    const bool edge = (bx == 0) | (by == 0) | (bx == 63) | (by == 63);

    if (!edge) {
        // ---- Phase A (interior): rotated 2x-resize, 2x2 outputs/thread ----
        for (int idx = t; idx < 35 * 36; idx += 256) {
            int c  = idx / 36;
            int m  = idx - c * 36;
            int jj = 2 * c + 1;
            int ii = 2 * m;
            int a  = 4095 - (j0 + jj);            // even
            int p  = a >> 1;
            const float* r0 = img + (size_t)(p - 1) * MM;
            const float* r1 = r0 + MM;
            int k = (i0 + ii) >> 1;
            float A0 = __ldg(&r0[k - 1]);
            float A1 = __ldg(&r0[k]);
            float A2 = __ldg(&r0[k + 1]);
            float B0 = __ldg(&r1[k - 1]);
            float B1 = __ldg(&r1[k]);
            float B2 = __ldg(&r1[k + 1]);
            float ea = fmaf(0.25f, A0, 0.75f * A1);
            float oa = fmaf(0.75f, A1, 0.25f * A2);
            float eb = fmaf(0.25f, B0, 0.75f * B1);
            float ob = fmaf(0.75f, B1, 0.25f * B2);
            float* s = s1 + ii * P1 + jj;
            s[0]      = fmaf(0.25f, ea, 0.75f * eb);
            s[1]      = fmaf(0.75f, ea, 0.25f * eb);
            s[P1]     = fmaf(0.25f, oa, 0.75f * ob);
            s[P1 + 1] = fmaf(0.75f, oa, 0.25f * ob);
        }
        // Leftover columns jj = 0 and jj = 71
        if (t < 72) {
            int col = t / 36;
            int m   = t - col * 36;
            int jj  = col ? (LJ - 1) : 0;
            int ii  = 2 * m;
            int a   = 4095 - (j0 + jj);
            int yf  = (a - 1) >> 1;
            float fy = (a & 1) ? 0.25f : 0.75f;
            const float* r0 = img + (size_t)yf * MM;
            const float* r1 = r0 + MM;
            int k = (i0 + ii) >> 1;
            float A0 = __ldg(&r0[k - 1]);
            float A1 = __ldg(&r0[k]);
            float A2 = __ldg(&r0[k + 1]);
            float B0 = __ldg(&r1[k - 1]);
            float B1 = __ldg(&r1[k]);
            float B2 = __ldg(&r1[k + 1]);
            float ea = fmaf(0.25f, A0, 0.75f * A1);
            float oa = fmaf(0.75f, A1, 0.25f * A2);
            float eb = fmaf(0.25f, B0, 0.75f * B1);
            float ob = fmaf(0.75f, B1, 0.25f * B2);
            s1[ii * P1 + jj]       = fmaf(fy, eb - ea, ea);
            s1[(ii + 1) * P1 + jj] = fmaf(fy, ob - oa, oa);
        }
        __syncthreads();

        // ---- Phase C (interior): noise fused into vertical blur, 8-row strips ----
        for (int idx = t; idx < 8 * LJ; idx += 256) {   // 576 tasks
            int g  = idx / LJ;
            int jj = idx - g * LJ;
            int ii = g * 8;
            const float* np = noise + (size_t)(i0 + ii) * NN + (j0 + jj);
            float v[16];
            #pragma unroll
            for (int r = 0; r < 16; r++)
                v[r] = fmaf(0.01f, __ldg(&np[(size_t)r * NN]), s1[(ii + r) * P1 + jj]);
            #pragma unroll
            for (int r = 0; r < 8; r++) {
                float acc = 0.0f;
                #pragma unroll
                for (int d = 0; d < 9; d++) acc = fmaf(KW[d], v[r + d], acc);
                s2[(ii + r) * P2 + jj] = acc;
            }
        }
    } else {
        // ---- Phase A (edge): symidx + clamps ----
        #pragma unroll 3
        for (int idx = t; idx < LI * LJ; idx += 256) {
            int jj = idx / LI;
            int ii = idx - jj * LI;
            int a  = NN - 1 - symidx(j0 + jj);
            int b  = symidx(i0 + ii);
            int yf = (a - 1) >> 1;
            int xf = (b - 1) >> 1;
            int y0 = max(yf, 0), y1 = min(yf + 1, MM - 1);
            int x0 = max(xf, 0), x1 = min(xf + 1, MM - 1);
            float fy = (a & 1) ? 0.25f : 0.75f;
            float fx = (b & 1) ? 0.25f : 0.75f;
            const float* r0 = img + (size_t)y0 * MM;
            const float* r1 = img + (size_t)y1 * MM;
            float v0 = __ldg(&r0[x0]);
            float v1 = __ldg(&r0[x1]);
            float w0 = __ldg(&r1[x0]);
            float w1 = __ldg(&r1[x1]);
            float h0 = fmaf(fx, v1 - v0, v0);
            float h1 = fmaf(fx, w1 - w0, w0);
            s1[ii * P1 + jj] = fmaf(fy, h1 - h0, h0);
        }
        __syncthreads();

        // ---- Phase B (edge): add noise with symidx ----
        #pragma unroll 3
        for (int idx = t; idx < LI * LJ; idx += 256) {
            int ii = idx / LJ;
            int jj = idx - ii * LJ;
            int gi = symidx(i0 + ii);
            int gj = symidx(j0 + jj);
            s1[ii * P1 + jj] += 0.01f * __ldg(&noise[(size_t)gi * NN + gj]);
        }
        __syncthreads();

        // ---- Phase C (edge): vertical blur, 8-row strips ----
        for (int idx = t; idx < 8 * LJ; idx += 256) {
            int g  = idx / LJ;
            int jj = idx - g * LJ;
            int ii = g * 8;
            float v[16];
            #pragma unroll
            for (int r = 0; r < 16; r++) v[r] = s1[(ii + r) * P1 + jj];
            #pragma unroll
            for (int r = 0; r < 8; r++) {
                float acc = 0.0f;
                #pragma unroll
                for (int d = 0; d < 9; d++) acc = fmaf(KW[d], v[r + d], acc);
                s2[(ii + r) * P2 + jj] = acc;
            }
        }
    }
    __syncthreads();

    // ---- Phase D: horizontal blur + clip + fast log1p, 4 outputs/thread ----
    // 1024 tasks = 4 exactly-dense rounds; 12-float window (3 LDS.128, conflict-free:
    // quarter-warp phase groups hit f4-columns {0..7} -> distinct bank quads).
    const int oi0 = by * TI;
    const int oj0 = bx * TJ;
    #pragma unroll
    for (int q = 0; q < 4; q++) {
        int idx = t + q * 256;
        int ii = idx >> 4;                  // 0..63
        int jj = (idx & 15) * 4;            // 0,4,...,60
        const float* row = &s2[ii * P2 + jj];
        float4 a0 = *(const float4*)(row);
        float4 a1 = *(const float4*)(row + 4);
        float4 a2 = *(const float4*)(row + 8);
        float v[12] = {a0.x, a0.y, a0.z, a0.w,
                       a1.x, a1.y, a1.z, a1.w,
                       a2.x, a2.y, a2.z, a2.w};
        float res[4];
        #pragma unroll
        for (int r = 0; r < 4; r++) {
            float acc = 0.0f;
            #pragma unroll
            for (int d = 0; d < 9; d++) acc = fmaf(KW[d], v[r + d], acc);
            res[r] = __logf(1.0f + fmaxf(acc, 0.0f));
        }
        *(float4*)&out[(size_t)(oi0 + ii) * NN + (oj0 + jj)] =
            make_float4(res[0], res[1], res[2], res[3]);
    }
}

extern "C" void kernel_launch(void* const* d_in, const int* in_sizes, int n_in,
                              void* d_out, int out_size) {
    const float* img   = (const float*)d_in[0];   // (1,2048,2048) f32
    const float* noise = (const float*)d_in[1];   // (1,4096,4096) f32
    if (n_in >= 2 && in_sizes[0] > in_sizes[1]) {
        const float* tmp = img; img = noise; noise = tmp;
    }
    dim3 grid(NN / TJ, NN / TI);
    fused_aug_kernel<<<grid, 256>>>(img, noise, (float*)d_out);
}

// round 17
// speedup vs baseline: 1.1363x; 1.0055x over previous
#include <cuda_runtime.h>
#include <cuda_bf16.h>

// out[i,j] = log1p(max(0, Gauss9 ⊛ T)),  T[i,j] = Resize2x(img)[N-1-j, i] + 0.01*noise[i,j]
// Resize2x = jax.image.resize 'linear' (half-pixel centers, 2x => weights {0.25,0.75}, edge clamp)
// Blur: separable 9-tap sigma=1 Gaussian, numpy 'symmetric' padding on T.

#define NN 4096
#define MM 2048
#define TI 64
#define TJ 64
#define HALO 4
#define LI (TI + 2*HALO)   // 72
#define LJ (TJ + 2*HALO)   // 72
#define P1T 76             // s1t pitch ([jj][ii] layout; mult of 4 for LDS.128; 19jj mod 8 distinct)
#define P2 76              // s2 pitch (mult of 4 -> aligned float4 loads)

__device__ __forceinline__ int symidx(int p) {
    p = (p < 0) ? (-1 - p) : p;
    return (p >= NN) ? (2 * NN - 1 - p) : p;
}

__global__ __launch_bounds__(256, 5)
void fused_aug_kernel(const float* __restrict__ img,
                      const float* __restrict__ noise,
                      float* __restrict__ out)
{
    // s1t is TRANSPOSED: s1t[jj * P1T + ii] holds T[ii][jj]
    __shared__ __align__(16) float s1t[LJ * P1T];
    __shared__ __align__(16) float s2[TI * P2];   // vertically blurred, row-major [ii][jj]

    const float KW[9] = {1.3383062e-4f, 4.4318616e-3f, 5.3991124e-2f,
                         2.4197145e-1f, 3.9894347e-1f, 2.4197145e-1f,
                         5.3991124e-2f, 4.4318616e-3f, 1.3383062e-4f};

    const int t  = threadIdx.x;
    const int bx = (int)blockIdx.x;
    const int by = (int)blockIdx.y;
    const int i0 = by * TI - HALO;
    const int j0 = bx * TJ - HALO;
    const bool edge = (bx == 0) | (by == 0) | (bx == 63) | (by == 63);

    if (!edge) {
        // ---- Phase A (interior): rotated 2x-resize, 2x2 outputs/thread, STS.64 stores ----
        for (int idx = t; idx < 35 * 36; idx += 256) {
            int c  = idx / 36;
            int m  = idx - c * 36;
            int jj = 2 * c + 1;
            int ii = 2 * m;
            int a  = 4095 - (j0 + jj);            // even
            int p  = a >> 1;
            const float* r0 = img + (size_t)(p - 1) * MM;
            const float* r1 = r0 + MM;
            int k = (i0 + ii) >> 1;
            float A0 = __ldg(&r0[k - 1]);
            float A1 = __ldg(&r0[k]);
            float A2 = __ldg(&r0[k + 1]);
            float B0 = __ldg(&r1[k - 1]);
            float B1 = __ldg(&r1[k]);
            float B2 = __ldg(&r1[k + 1]);
            float ea = fmaf(0.25f, A0, 0.75f * A1);
            float oa = fmaf(0.75f, A1, 0.25f * A2);
            float eb = fmaf(0.25f, B0, 0.75f * B1);
            float ob = fmaf(0.75f, B1, 0.25f * B2);
            // row jj gets (T[ii][jj], T[ii+1][jj]); row jj+1 gets (T[ii][jj+1], T[ii+1][jj+1])
            *(float2*)(s1t + jj * P1T + ii) =
                make_float2(fmaf(0.25f, ea, 0.75f * eb), fmaf(0.25f, oa, 0.75f * ob));
            *(float2*)(s1t + (jj + 1) * P1T + ii) =
                make_float2(fmaf(0.75f, ea, 0.25f * eb), fmaf(0.75f, oa, 0.25f * ob));
        }
        // Leftover columns jj = 0 and jj = 71
        if (t < 72) {
            int col = t / 36;
            int m   = t - col * 36;
            int jj  = col ? (LJ - 1) : 0;
            int ii  = 2 * m;
            int a   = 4095 - (j0 + jj);
            int yf  = (a - 1) >> 1;
            float fy = (a & 1) ? 0.25f : 0.75f;
            const float* r0 = img + (size_t)yf * MM;
            const float* r1 = r0 + MM;
            int k = (i0 + ii) >> 1;
            float A0 = __ldg(&r0[k - 1]);
            float A1 = __ldg(&r0[k]);
            float A2 = __ldg(&r0[k + 1]);
            float B0 = __ldg(&r1[k - 1]);
            float B1 = __ldg(&r1[k]);
            float B2 = __ldg(&r1[k + 1]);
            float ea = fmaf(0.25f, A0, 0.75f * A1);
            float oa = fmaf(0.75f, A1, 0.25f * A2);
            float eb = fmaf(0.25f, B0, 0.75f * B1);
            float ob = fmaf(0.75f, B1, 0.25f * B2);
            *(float2*)(s1t + jj * P1T + ii) =
                make_float2(fmaf(fy, eb - ea, ea), fmaf(fy, ob - oa, oa));
        }
        __syncthreads();

        // ---- Phase C (interior): noise fused into vertical blur, 8-row strips, LDS.128 ----
        for (int idx = t; idx < 8 * LJ; idx += 256) {   // 576 tasks
            int g  = idx / LJ;
            int jj = idx - g * LJ;
            int ii = g * 8;
            const float*  np = noise + (size_t)(i0 + ii) * NN + (j0 + jj);
            const float4* sp = (const float4*)(s1t + jj * P1T + ii);  // 16B-aligned (ii mult of 8)
            float4 t0 = sp[0];
            float4 t1 = sp[1];
            float4 t2 = sp[2];
            float4 t3 = sp[3];
            float v[16] = {t0.x, t0.y, t0.z, t0.w,  t1.x, t1.y, t1.z, t1.w,
                           t2.x, t2.y, t2.z, t2.w,  t3.x, t3.y, t3.z, t3.w};
            #pragma unroll
            for (int r = 0; r < 16; r++)
                v[r] = fmaf(0.01f, __ldg(&np[(size_t)r * NN]), v[r]);
            #pragma unroll
            for (int r = 0; r < 8; r++) {
                float acc = 0.0f;
                #pragma unroll
                for (int d = 0; d < 9; d++) acc = fmaf(KW[d], v[r + d], acc);
                s2[(ii + r) * P2 + jj] = acc;
            }
        }
    } else {
        // ---- Phase A (edge): symidx + clamps, transposed scalar stores (stride-1 per warp) ----
        #pragma unroll 3
        for (int idx = t; idx < LI * LJ; idx += 256) {
            int jj = idx / LI;
            int ii = idx - jj * LI;
            int a  = NN - 1 - symidx(j0 + jj);
            int b  = symidx(i0 + ii);
            int yf = (a - 1) >> 1;
            int xf = (b - 1) >> 1;
            int y0 = max(yf, 0), y1 = min(yf + 1, MM - 1);
            int x0 = max(xf, 0), x1 = min(xf + 1, MM - 1);
            float fy = (a & 1) ? 0.25f : 0.75f;
            float fx = (b & 1) ? 0.25f : 0.75f;
            const float* r0 = img + (size_t)y0 * MM;
            const float* r1 = img + (size_t)y1 * MM;
            float v0 = __ldg(&r0[x0]);
            float v1 = __ldg(&r0[x1]);
            float w0 = __ldg(&r1[x0]);
            float w1 = __ldg(&r1[x1]);
            float h0 = fmaf(fx, v1 - v0, v0);
            float h1 = fmaf(fx, w1 - w0, w0);
            s1t[jj * P1T + ii] = fmaf(fy, h1 - h0, h0);
        }
        __syncthreads();

        // ---- Phase B (edge): add noise with symidx (noise coalesced; smem strided) ----
        #pragma unroll 3
        for (int idx = t; idx < LI * LJ; idx += 256) {
            int ii = idx / LJ;
            int jj = idx - ii * LJ;
            int gi = symidx(i0 + ii);
            int gj = symidx(j0 + jj);
            s1t[jj * P1T + ii] += 0.01f * __ldg(&noise[(size_t)gi * NN + gj]);
        }
        __syncthreads();

        // ---- Phase C (edge): vertical blur, 8-row strips, LDS.128 ----
        for (int idx = t; idx < 8 * LJ; idx += 256) {
            int g  = idx / LJ;
            int jj = idx - g * LJ;
            int ii = g * 8;
            const float4* sp = (const float4*)(s1t + jj * P1T + ii);
            float4 t0 = sp[0];
            float4 t1 = sp[1];
            float4 t2 = sp[2];
            float4 t3 = sp[3];
            float v[16] = {t0.x, t0.y, t0.z, t0.w,  t1.x, t1.y, t1.z, t1.w,
                           t2.x, t2.y, t2.z, t2.w,  t3.x, t3.y, t3.z, t3.w};
            #pragma unroll
            for (int r = 0; r < 8; r++) {
                float acc = 0.0f;
                #pragma unroll
                for (int d = 0; d < 9; d++) acc = fmaf(KW[d], v[r + d], acc);
                s2[(ii + r) * P2 + jj] = acc;
            }
        }
    }
    __syncthreads();

    // ---- Phase D: horizontal blur + clip + fast log1p, 4 outputs/thread ----
    // 1024 tasks = 4 exactly-dense rounds; 12-float window, conflict-free LDS.128.
    const int oi0 = by * TI;
    const int oj0 = bx * TJ;
    #pragma unroll
    for (int q = 0; q < 4; q++) {
        int idx = t + q * 256;
        int ii = idx >> 4;                  // 0..63
        int jj = (idx & 15) * 4;            // 0,4,...,60
        const float* row = &s2[ii * P2 + jj];
        float4 a0 = *(const float4*)(row);
        float4 a1 = *(const float4*)(row + 4);
        float4 a2 = *(const float4*)(row + 8);
        float v[12] = {a0.x, a0.y, a0.z, a0.w,
                       a1.x, a1.y, a1.z, a1.w,
                       a2.x, a2.y, a2.z, a2.w};
        float res[4];
        #pragma unroll
        for (int r = 0; r < 4; r++) {
            float acc = 0.0f;
            #pragma unroll
            for (int d = 0; d < 9; d++) acc = fmaf(KW[d], v[r + d], acc);
            res[r] = __logf(1.0f + fmaxf(acc, 0.0f));
        }
        *(float4*)&out[(size_t)(oi0 + ii) * NN + (oj0 + jj)] =
            make_float4(res[0], res[1], res[2], res[3]);
    }
}

extern "C" void kernel_launch(void* const* d_in, const int* in_sizes, int n_in,
                              void* d_out, int out_size) {
    const float* img   = (const float*)d_in[0];   // (1,2048,2048) f32
    const float* noise = (const float*)d_in[1];   // (1,4096,4096) f32
    if (n_in >= 2 && in_sizes[0] > in_sizes[1]) {
        const float* tmp = img; img = noise; noise = tmp;
    }
    dim3 grid(NN / TJ, NN / TI);
    fused_aug_kernel<<<grid, 256>>>(img, noise, (float*)d_out);
}